// round 12
// baseline (speedup 1.0000x reference)
#include <cuda_runtime.h>
#include <cuda_fp16.h>
#include <math_constants.h>

#define BATCH 1024
#define NGENE 8192
#define NSETS 2048
#define MAX_TOTAL 262144   // >= 2048 * 120

// Scratch (static device globals — no runtime allocation)
__device__ __half g_GT[NGENE * BATCH];    // transposed features, fp16, 16.8 MB
__device__ int2   g_pair[MAX_TOTAL];      // {gene byte offset, weight bits}, 2 MB
__device__ int    g_off[NSETS + 1];       // segment start offsets

// ---------------------------------------------------------------------------
// K0: segment boundary detection (segment_ids sorted, all segments nonempty).
// ---------------------------------------------------------------------------
__global__ void k_offsets(const int* __restrict__ seg, int total) {
    int p = blockIdx.x * blockDim.x + threadIdx.x;
    if (p >= total) return;
    if (p == 0) g_off[0] = 0;
    else {
        int s = seg[p];
        if (seg[p - 1] != s) g_off[s] = p;
    }
    if (p == total - 1) g_off[NSETS] = total;
}

// ---------------------------------------------------------------------------
// K1 (fused): heterogeneous grid.
//   blocks [0, 256)      : warp-per-segment softmax -> g_pair   (needs g_off)
//   blocks [256, 256+8192): 32x32 transpose tiles  G f32 -> GT f16
// The two works are independent; softmax blocks are first so they overlap
// with the DRAM-bound transpose instead of costing their own launch.
// blockDim (32,8).
// ---------------------------------------------------------------------------
__global__ void k_prep(const float* __restrict__ G,
                       const float* __restrict__ logits,
                       const int* __restrict__ fidx) {
    int bid = blockIdx.x;
    if (bid < 256) {
        // ---- softmax part ----
        int tid  = threadIdx.y * 32 + threadIdx.x;
        int warp_id = bid * 8 + (tid >> 5);
        int lane = tid & 31;
        int beg = g_off[warp_id];
        int end = g_off[warp_id + 1];

        float m = -CUDART_INF_F;
        for (int p = beg + lane; p < end; p += 32) m = fmaxf(m, logits[p]);
        #pragma unroll
        for (int o = 16; o; o >>= 1) m = fmaxf(m, __shfl_xor_sync(0xFFFFFFFFu, m, o));

        float sum = 0.0f;
        for (int p = beg + lane; p < end; p += 32) sum += __expf(logits[p] - m);
        #pragma unroll
        for (int o = 16; o; o >>= 1) sum += __shfl_xor_sync(0xFFFFFFFFu, sum, o);

        float inv = (sum > 0.0f) ? (1.0f / sum) : 0.0f;
        for (int p = beg + lane; p < end; p += 32) {
            float w = __expf(logits[p] - m) * inv;
            g_pair[p] = make_int2(fidx[p] * (BATCH * 2), __float_as_int(w));
        }
    } else {
        // ---- transpose part ----
        int tb = bid - 256;
        __shared__ float tile[32][33];
        int gx = (tb & 255) * 32;   // gene base   (NGENE/32 = 256)
        int by = (tb >> 8) * 32;    // batch base  (BATCH/32 = 32)
        int x = gx + threadIdx.x;
        #pragma unroll
        for (int j = 0; j < 32; j += 8)
            tile[threadIdx.y + j][threadIdx.x] = G[(by + threadIdx.y + j) * NGENE + x];
        __syncthreads();
        #pragma unroll
        for (int j = 0; j < 32; j += 8)
            g_GT[(gx + threadIdx.y + j) * BATCH + by + threadIdx.x] =
                __float2half_rn(tile[threadIdx.x][threadIdx.y + j]);
    }
}

// ---------------------------------------------------------------------------
// K2: 2D-tiled aggregation writing out directly; batch-tile = 512.
// grid = (NSETS/8 = 256, BATCH/512 = 2) -> 512 blocks, ALL resident at once.
// Warp w owns set s0+w over rows b0..b0+511. Per edge, each thread issues
// TWO structurally independent LDG.128s (rows lane*8 and 256+lane*8), so a
// 4-wide edge unroll keeps 8 gathers in flight regardless of ptxas's
// scheduling appetite. Per-edge descriptor traffic also halves (2 batch
// tiles instead of 4). Result tile (8 x 512) staged in 16KB smem, written
// as fully-coalesced 32B chunks out[b][s0..s0+7].
// ---------------------------------------------------------------------------
__device__ __forceinline__ void fma8(float4& a0, float4& a1, uint4 u, float w) {
    float2 v;
    v = __half22float2(*reinterpret_cast<const __half2*>(&u.x));
    a0.x += w * v.x;  a0.y += w * v.y;
    v = __half22float2(*reinterpret_cast<const __half2*>(&u.y));
    a0.z += w * v.x;  a0.w += w * v.y;
    v = __half22float2(*reinterpret_cast<const __half2*>(&u.z));
    a1.x += w * v.x;  a1.y += w * v.y;
    v = __half22float2(*reinterpret_cast<const __half2*>(&u.w));
    a1.z += w * v.x;  a1.w += w * v.y;
}

__global__ __launch_bounds__(256) void k_agg(float* __restrict__ out) {
    int t    = threadIdx.x;
    int warp = t >> 5;
    int lane = t & 31;
    int s0   = blockIdx.x * 8;
    int b0   = blockIdx.y * 512;
    int s    = s0 + warp;

    int beg = g_off[s];
    int n   = g_off[s + 1] - beg;
    if (n > 128) n = 128;             // structural: n <= 120

    // Thread covers rows (b0 + lane*8 .. +7) and (b0+256 + lane*8 .. +7)
    const char* gt = reinterpret_cast<const char*>(g_GT) + b0 * 2 + lane * 16;
    const int2* pr = g_pair + beg;

    float4 a0 = make_float4(0.f, 0.f, 0.f, 0.f);
    float4 a1 = make_float4(0.f, 0.f, 0.f, 0.f);
    float4 a2 = make_float4(0.f, 0.f, 0.f, 0.f);
    float4 a3 = make_float4(0.f, 0.f, 0.f, 0.f);

    int i = 0;
    for (; i + 4 <= n; i += 4) {
        int2 p0 = pr[i + 0];
        int2 p1 = pr[i + 1];
        int2 p2 = pr[i + 2];
        int2 p3 = pr[i + 3];
        uint4 uA0 = *reinterpret_cast<const uint4*>(gt + p0.x);
        uint4 uB0 = *reinterpret_cast<const uint4*>(gt + p0.x + 512);
        uint4 uA1 = *reinterpret_cast<const uint4*>(gt + p1.x);
        uint4 uB1 = *reinterpret_cast<const uint4*>(gt + p1.x + 512);
        uint4 uA2 = *reinterpret_cast<const uint4*>(gt + p2.x);
        uint4 uB2 = *reinterpret_cast<const uint4*>(gt + p2.x + 512);
        uint4 uA3 = *reinterpret_cast<const uint4*>(gt + p3.x);
        uint4 uB3 = *reinterpret_cast<const uint4*>(gt + p3.x + 512);
        float w0 = __int_as_float(p0.y), w1 = __int_as_float(p1.y);
        float w2 = __int_as_float(p2.y), w3 = __int_as_float(p3.y);
        fma8(a0, a1, uA0, w0);  fma8(a2, a3, uB0, w0);
        fma8(a0, a1, uA1, w1);  fma8(a2, a3, uB1, w1);
        fma8(a0, a1, uA2, w2);  fma8(a2, a3, uB2, w2);
        fma8(a0, a1, uA3, w3);  fma8(a2, a3, uB3, w3);
    }
    for (; i < n; i++) {
        int2 p = pr[i];
        uint4 uA = *reinterpret_cast<const uint4*>(gt + p.x);
        uint4 uB = *reinterpret_cast<const uint4*>(gt + p.x + 512);
        float w = __int_as_float(p.y);
        fma8(a0, a1, uA, w);
        fma8(a2, a3, uB, w);
    }

    // Stage tile: buf[set][local row 0..511]
    __shared__ float buf[8][512];
    *reinterpret_cast<float4*>(&buf[warp][lane * 8 + 0])       = a0;
    *reinterpret_cast<float4*>(&buf[warp][lane * 8 + 4])       = a1;
    *reinterpret_cast<float4*>(&buf[warp][256 + lane * 8 + 0]) = a2;
    *reinterpret_cast<float4*>(&buf[warp][256 + lane * 8 + 4]) = a3;
    __syncthreads();

    // Coalesced output: thread t covers local rows t and t+256
    #pragma unroll
    for (int r = 0; r < 2; r++) {
        int lb = t + r * 256;
        float4 o0, o1;
        o0.x = buf[0][lb]; o0.y = buf[1][lb]; o0.z = buf[2][lb]; o0.w = buf[3][lb];
        o1.x = buf[4][lb]; o1.y = buf[5][lb]; o1.z = buf[6][lb]; o1.w = buf[7][lb];
        float* dst = out + (size_t)(b0 + lb) * NSETS + s0;
        *reinterpret_cast<float4*>(dst)     = o0;
        *reinterpret_cast<float4*>(dst + 4) = o1;
    }
}

// ---------------------------------------------------------------------------
// Launcher (graph-capturable: kernel launches only, default stream ordering)
// ---------------------------------------------------------------------------
extern "C" void kernel_launch(void* const* d_in, const int* in_sizes, int n_in,
                              void* d_out, int out_size) {
    const float* G      = (const float*)d_in[0];
    const float* logits = (const float*)d_in[1];
    const int*   fidx   = (const int*)d_in[2];
    const int*   seg    = (const int*)d_in[3];
    float*       out    = (float*)d_out;
    int total = in_sizes[1];

    k_offsets<<<(total + 255) / 256, 256>>>(seg, total);
    k_prep<<<256 + (NGENE / 32) * (BATCH / 32), dim3(32, 8)>>>(G, logits, fidx);
    k_agg<<<dim3(NSETS / 8, BATCH / 512), 256>>>(out);
}

// round 13
// speedup vs baseline: 1.1174x; 1.1174x over previous
#include <cuda_runtime.h>
#include <cuda_fp16.h>
#include <math_constants.h>

#define BATCH 1024
#define NGENE 8192
#define NSETS 2048
#define MAX_TOTAL 262144   // >= 2048 * 120

// Scratch (static device globals — no runtime allocation)
__device__ __half g_GT[NGENE * BATCH];    // transposed features, fp16, 16.8 MB
__device__ int2   g_pair[MAX_TOTAL];      // {gene byte offset, weight bits}, 2 MB
__device__ int    g_off[NSETS + 1];       // segment start offsets

// ---------------------------------------------------------------------------
// K0: segment boundary detection, vectorized: each thread scans 4 positions
// via one int4 + one scalar predecessor load (both independent -> 2-deep MLP,
// 1/4 the instruction count of the scalar version measured at 4.1us).
// ---------------------------------------------------------------------------
__global__ void k_offsets(const int* __restrict__ seg, int total) {
    int i = blockIdx.x * blockDim.x + threadIdx.x;
    int p = i * 4;
    if (p >= total) return;
    if (i == 0) {
        g_off[0] = 0;
        g_off[NSETS] = total;
    }
    if (p + 4 <= total) {
        int prev = (p == 0) ? 0 : seg[p - 1];   // seg[0] == 0 structurally
        int4 v = *reinterpret_cast<const int4*>(seg + p);
        if (v.x != prev) g_off[v.x] = p;
        if (v.y != v.x)  g_off[v.y] = p + 1;
        if (v.z != v.y)  g_off[v.z] = p + 2;
        if (v.w != v.z)  g_off[v.w] = p + 3;
    } else {
        for (int q = p; q < total; q++) {
            if (q > 0) {
                int s = seg[q];
                if (seg[q - 1] != s) g_off[s] = q;
            }
        }
    }
}

// ---------------------------------------------------------------------------
// K1 (fused): heterogeneous grid.
//   blocks [0, 256)       : warp-per-segment softmax -> g_pair  (needs g_off)
//   blocks [256, 256+8192): 32x32 transpose tiles  G f32 -> GT f16
// Independent works; softmax hides under the DRAM-bound transpose.
// blockDim (32,8).
// ---------------------------------------------------------------------------
__global__ void k_prep(const float* __restrict__ G,
                       const float* __restrict__ logits,
                       const int* __restrict__ fidx) {
    int bid = blockIdx.x;
    if (bid < 256) {
        // ---- softmax part ----
        int tid  = threadIdx.y * 32 + threadIdx.x;
        int warp_id = bid * 8 + (tid >> 5);
        int lane = tid & 31;
        int beg = g_off[warp_id];
        int end = g_off[warp_id + 1];

        float m = -CUDART_INF_F;
        for (int p = beg + lane; p < end; p += 32) m = fmaxf(m, logits[p]);
        #pragma unroll
        for (int o = 16; o; o >>= 1) m = fmaxf(m, __shfl_xor_sync(0xFFFFFFFFu, m, o));

        float sum = 0.0f;
        for (int p = beg + lane; p < end; p += 32) sum += __expf(logits[p] - m);
        #pragma unroll
        for (int o = 16; o; o >>= 1) sum += __shfl_xor_sync(0xFFFFFFFFu, sum, o);

        float inv = (sum > 0.0f) ? (1.0f / sum) : 0.0f;
        for (int p = beg + lane; p < end; p += 32) {
            float w = __expf(logits[p] - m) * inv;
            g_pair[p] = make_int2(fidx[p] * (BATCH * 2), __float_as_int(w));
        }
    } else {
        // ---- transpose part ----
        int tb = bid - 256;
        __shared__ float tile[32][33];
        int gx = (tb & 255) * 32;   // gene base   (NGENE/32 = 256)
        int by = (tb >> 8) * 32;    // batch base  (BATCH/32 = 32)
        int x = gx + threadIdx.x;
        #pragma unroll
        for (int j = 0; j < 32; j += 8)
            tile[threadIdx.y + j][threadIdx.x] = G[(by + threadIdx.y + j) * NGENE + x];
        __syncthreads();
        #pragma unroll
        for (int j = 0; j < 32; j += 8)
            g_GT[(gx + threadIdx.y + j) * BATCH + by + threadIdx.x] =
                __float2half_rn(tile[threadIdx.x][threadIdx.y + j]);
    }
}

// ---------------------------------------------------------------------------
// K2: 2D-tiled aggregation writing out directly (round-11 exact: 33.5us).
// grid = (NSETS/8, BATCH/256), block = 256 threads.
// Warp w owns set s0+w over batch rows b0..b0+255; thread = 8 rows (uint4).
// Result tile (8 sets x 256 rows) staged in 8KB smem, then written as
// fully-coalesced 32B chunks: out[b0+t][s0..s0+7].
// ---------------------------------------------------------------------------
__device__ __forceinline__ void fma8(float4& a0, float4& a1, uint4 u, float w) {
    float2 v;
    v = __half22float2(*reinterpret_cast<const __half2*>(&u.x));
    a0.x += w * v.x;  a0.y += w * v.y;
    v = __half22float2(*reinterpret_cast<const __half2*>(&u.y));
    a0.z += w * v.x;  a0.w += w * v.y;
    v = __half22float2(*reinterpret_cast<const __half2*>(&u.z));
    a1.x += w * v.x;  a1.y += w * v.y;
    v = __half22float2(*reinterpret_cast<const __half2*>(&u.w));
    a1.z += w * v.x;  a1.w += w * v.y;
}

__global__ __launch_bounds__(256) void k_agg(float* __restrict__ out) {
    int t    = threadIdx.x;
    int warp = t >> 5;
    int lane = t & 31;
    int s0   = blockIdx.x * 8;
    int b0   = blockIdx.y * 256;
    int s    = s0 + warp;

    int beg = g_off[s];
    int n   = g_off[s + 1] - beg;
    if (n > 128) n = 128;             // structural: n <= 120

    const char* gt = reinterpret_cast<const char*>(g_GT) + b0 * 2 + lane * 16;
    const int2* pr = g_pair + beg;

    float4 a0 = make_float4(0.f, 0.f, 0.f, 0.f);
    float4 a1 = make_float4(0.f, 0.f, 0.f, 0.f);

    int i = 0;
    for (; i + 8 <= n; i += 8) {
        int2 p[8];
        #pragma unroll
        for (int k = 0; k < 8; k++) p[k] = pr[i + k];
        uint4 u[8];
        #pragma unroll
        for (int k = 0; k < 8; k++)
            u[k] = *reinterpret_cast<const uint4*>(gt + p[k].x);
        #pragma unroll
        for (int k = 0; k < 8; k++)
            fma8(a0, a1, u[k], __int_as_float(p[k].y));
    }
    for (; i < n; i++) {
        int2 p = pr[i];
        uint4 u = *reinterpret_cast<const uint4*>(gt + p.x);
        fma8(a0, a1, u, __int_as_float(p.y));
    }

    // Stage tile: buf[set][local batch row]; thread's rows are 8*lane..8*lane+7
    __shared__ float buf[8][256];
    *reinterpret_cast<float4*>(&buf[warp][lane * 8 + 0]) = a0;
    *reinterpret_cast<float4*>(&buf[warp][lane * 8 + 4]) = a1;
    __syncthreads();

    // Coalesced output: thread t writes out[b0+t][s0..s0+7] (32B, sector-full)
    float4 o0, o1;
    o0.x = buf[0][t]; o0.y = buf[1][t]; o0.z = buf[2][t]; o0.w = buf[3][t];
    o1.x = buf[4][t]; o1.y = buf[5][t]; o1.z = buf[6][t]; o1.w = buf[7][t];
    float* dst = out + (size_t)(b0 + t) * NSETS + s0;
    *reinterpret_cast<float4*>(dst)     = o0;
    *reinterpret_cast<float4*>(dst + 4) = o1;
}

// ---------------------------------------------------------------------------
// Launcher (graph-capturable: kernel launches only, default stream ordering)
// ---------------------------------------------------------------------------
extern "C" void kernel_launch(void* const* d_in, const int* in_sizes, int n_in,
                              void* d_out, int out_size) {
    const float* G      = (const float*)d_in[0];
    const float* logits = (const float*)d_in[1];
    const int*   fidx   = (const int*)d_in[2];
    const int*   seg    = (const int*)d_in[3];
    float*       out    = (float*)d_out;
    int total = in_sizes[1];

    k_offsets<<<(total / 4 + 255) / 256, 256>>>(seg, total);
    k_prep<<<256 + (NGENE / 32) * (BATCH / 32), dim3(32, 8)>>>(G, logits, fidx);
    k_agg<<<dim3(NSETS / 8, BATCH / 256), 256>>>(out);
}